// round 10
// baseline (speedup 1.0000x reference)
#include <cuda_runtime.h>
#include <math.h>
#include <stddef.h>
#include <stdint.h>

#define Nn   12288
#define Dd   128
#define DOUT 64
#define KNN  20
#define TK   28                  // over-fetched candidate count (exact-rescored)
#define EE   (Nn*KNN)
#define NTILES (Nn/128)          // 96

// ---- scratch (static device allocations; no cudaMalloc anywhere) ----
__device__ float g_xn [Nn*Dd];                 // normalized x, full fp32 (for exact rescore)
__device__ float g_xhi[Nn*Dd];                 // tf32-rounded normalized x
__device__ float g_xlo[Nn*Dd];                 // tf32-rounded residual
__device__ float g_adj[(size_t)Nn*Nn];         // 604 MB cosine-sim matrix
__device__ float g_topv[EE];
__device__ int   g_topi[EE];
__device__ float g_deg[Nn];
__device__ float g_dis[Nn];
__device__ float g_hw1[Nn*Dd];
__device__ float g_hagg[Nn*Dd];
__device__ float g_hw2[Nn*DOUT];

// =====================================================================
__device__ __forceinline__ float to_tf32(float x) {
    uint32_t b;
    asm("cvt.rna.tf32.f32 %0, %1;" : "=r"(b) : "f"(x));
    return __uint_as_float(b);
}

__device__ __forceinline__ void mma_tf32(float* c, const float* a, const float* b) {
    asm volatile(
        "mma.sync.aligned.m16n8k8.row.col.f32.tf32.tf32.f32 "
        "{%0,%1,%2,%3}, {%4,%5,%6,%7}, {%8,%9}, {%0,%1,%2,%3};"
        : "+f"(c[0]), "+f"(c[1]), "+f"(c[2]), "+f"(c[3])
        : "r"(__float_as_uint(a[0])), "r"(__float_as_uint(a[1])),
          "r"(__float_as_uint(a[2])), "r"(__float_as_uint(a[3])),
          "r"(__float_as_uint(b[0])), "r"(__float_as_uint(b[1])));
}

// =====================================================================
// init: seed h_agg with b1, out with b2, zero deg
__global__ void k_init(const float* __restrict__ b1, const float* __restrict__ b2,
                       float* __restrict__ out) {
    int i = blockIdx.x*256 + threadIdx.x;
    if (i < Nn*Dd)   g_hagg[i] = b1[i & (Dd-1)];
    if (i < Nn*DOUT) out[i]    = b2[i & (DOUT-1)];
    if (i < Nn)      g_deg[i]  = 0.f;
}

// =====================================================================
// row normalize: write fp32 copy + tf32 hi/lo split. One warp per row.
__global__ void k_rownorm(const float* __restrict__ x) {
    int warp = threadIdx.x >> 5, lane = threadIdx.x & 31;
    int r = blockIdx.x*8 + warp;
    float4 v = ((const float4*)x)[r*(Dd/4) + lane];
    float ss = v.x*v.x + v.y*v.y + v.z*v.z + v.w*v.w;
    #pragma unroll
    for (int o = 16; o; o >>= 1) ss += __shfl_xor_sync(0xffffffffu, ss, o);
    float s = 1.f / fmaxf(sqrtf(ss), 1e-12f);
    float4 w4 = make_float4(v.x*s, v.y*s, v.z*s, v.w*s);
    ((float4*)g_xn)[r*32 + lane] = w4;
    float* wp = (float*)&w4;
    float4 hi, lo;
    float* hp = (float*)&hi; float* lp = (float*)&lo;
    #pragma unroll
    for (int j = 0; j < 4; j++) {
        hp[j] = to_tf32(wp[j]);
        lp[j] = to_tf32(wp[j] - hp[j]);
    }
    ((float4*)g_xhi)[r*32 + lane] = hi;
    ((float4*)g_xlo)[r*32 + lane] = lo;
}

// =====================================================================
// adj ~= xn @ xn^T via tf32 mma.sync (3-term hi/lo), triangle + mirror.
// Values used ONLY for candidate generation (top-28); exact rescore follows.
#define TSTRIDE 68   // padded smem row stride (floats) -> conflict-free frags

__global__ void __launch_bounds__(256) k_adj() {
    int bx = blockIdx.x, by = blockIdx.y;
    if (by > bx) return;

    extern __shared__ float sm[];
    float* Ah = sm;
    float* Al = Ah + 128*TSTRIDE;
    float* Bh = Al + 128*TSTRIDE;
    float* Bl = Bh + 128*TSTRIDE;

    int tid  = threadIdx.x;
    int wid  = tid >> 5, lane = tid & 31;
    int g    = lane >> 2, tig = lane & 3;
    int wm   = (wid & 1) * 64;
    int wn   = (wid >> 1) * 32;
    int rb   = by * 128, cb = bx * 128;

    float acc[4][4][4];
    #pragma unroll
    for (int mi = 0; mi < 4; mi++)
        #pragma unroll
        for (int ni = 0; ni < 4; ni++)
            #pragma unroll
            for (int q = 0; q < 4; q++) acc[mi][ni][q] = 0.f;

    for (int ch = 0; ch < 2; ch++) {
        if (ch) __syncthreads();
        #pragma unroll
        for (int t = 0; t < 8; t++) {
            int idx = tid + t*256;
            int row = idx >> 4, q = idx & 15;
            size_t gA = (size_t)(rb + row)*Dd + ch*64 + q*4;
            size_t gB = (size_t)(cb + row)*Dd + ch*64 + q*4;
            int so = row*TSTRIDE + q*4;
            *(float4*)&Ah[so] = *(const float4*)&g_xhi[gA];
            *(float4*)&Al[so] = *(const float4*)&g_xlo[gA];
            *(float4*)&Bh[so] = *(const float4*)&g_xhi[gB];
            *(float4*)&Bl[so] = *(const float4*)&g_xlo[gB];
        }
        __syncthreads();

        #pragma unroll
        for (int ks = 0; ks < 8; ks++) {
            int k0 = ks*8;
            float ah[4][4], al[4][4], bh[4][2], bl[4][2];
            #pragma unroll
            for (int mi = 0; mi < 4; mi++) {
                int base = (wm + mi*16 + g)*TSTRIDE + k0 + tig;
                ah[mi][0] = Ah[base];             ah[mi][1] = Ah[base + 8*TSTRIDE];
                ah[mi][2] = Ah[base + 4];         ah[mi][3] = Ah[base + 8*TSTRIDE + 4];
                al[mi][0] = Al[base];             al[mi][1] = Al[base + 8*TSTRIDE];
                al[mi][2] = Al[base + 4];         al[mi][3] = Al[base + 8*TSTRIDE + 4];
            }
            #pragma unroll
            for (int ni = 0; ni < 4; ni++) {
                int base = (wn + ni*8 + g)*TSTRIDE + k0 + tig;
                bh[ni][0] = Bh[base];  bh[ni][1] = Bh[base + 4];
                bl[ni][0] = Bl[base];  bl[ni][1] = Bl[base + 4];
            }
            #pragma unroll
            for (int mi = 0; mi < 4; mi++)
                #pragma unroll
                for (int ni = 0; ni < 4; ni++) {
                    mma_tf32(acc[mi][ni], ah[mi], bh[ni]);
                    mma_tf32(acc[mi][ni], ah[mi], bl[ni]);
                    mma_tf32(acc[mi][ni], al[mi], bh[ni]);
                }
        }
    }

    #pragma unroll
    for (int mi = 0; mi < 4; mi++)
        #pragma unroll
        for (int ni = 0; ni < 4; ni++) {
            int r0 = wm + mi*16 + g;
            int c0 = wn + ni*8 + tig*2;
            size_t base = (size_t)(rb + r0)*Nn + cb + c0;
            *(float2*)&g_adj[base]                = make_float2(acc[mi][ni][0], acc[mi][ni][1]);
            *(float2*)&g_adj[base + 8*(size_t)Nn] = make_float2(acc[mi][ni][2], acc[mi][ni][3]);
            if (bx != by) {
                size_t mb = (size_t)(cb + c0)*Nn + rb + r0;
                g_adj[mb]          = acc[mi][ni][0];
                g_adj[mb + Nn]     = acc[mi][ni][1];
                g_adj[mb + 8]      = acc[mi][ni][2];
                g_adj[mb + Nn + 8] = acc[mi][ni][3];
            }
        }
}

// =====================================================================
// top-28 candidates per row (tf32 values) -> exact serial-fp32 rescore ->
// re-rank by (value desc, index asc) like jax top_k -> select top-20,
// store exact weights, accumulate deg. One warp per row.
__device__ __forceinline__ float topk_insert(float* lv, int* li, float v, int c) {
    int p = TK-1;
    while (p > 0 && lv[p-1] < v) { lv[p] = lv[p-1]; li[p] = li[p-1]; p--; }
    lv[p] = v; li[p] = c;
    return lv[TK-1];
}

__global__ void k_topk() {
    int warp = threadIdx.x >> 5, lane = threadIdx.x & 31;
    int r = blockIdx.x*8 + warp;
    float lv[TK]; int li[TK];
    #pragma unroll
    for (int k = 0; k < TK; k++) { lv[k] = -INFINITY; li[k] = 0x7fffffff; }
    float thresh = -INFINITY;
    const float4* rowp = (const float4*)(g_adj + (size_t)r*Nn);
    for (int it = 0; it < Nn/128; it++) {
        float4 v = rowp[it*32 + lane];
        int cbx = (it*32 + lane)*4;
        if (v.x > thresh) thresh = topk_insert(lv, li, v.x, cbx+0);
        if (v.y > thresh) thresh = topk_insert(lv, li, v.y, cbx+1);
        if (v.z > thresh) thresh = topk_insert(lv, li, v.z, cbx+2);
        if (v.w > thresh) thresh = topk_insert(lv, li, v.w, cbx+3);
    }

    // ---- extract global top-TK (by tf32 value) into lane slots 0..TK-1
    int pi = 0;
    int seli = 0x7fffffff;
    for (int k = 0; k < TK; k++) {
        float bv = (pi < TK) ? lv[pi] : -INFINITY;
        int   bl = lane;
        #pragma unroll
        for (int o = 16; o; o >>= 1) {
            float ov = __shfl_xor_sync(0xffffffffu, bv, o);
            int   ol = __shfl_xor_sync(0xffffffffu, bl, o);
            if (ov > bv || (ov == bv && ol < bl)) { bv = ov; bl = ol; }
        }
        int myci   = (pi < TK) ? li[pi] : 0x7fffffff;
        int cand_i = __shfl_sync(0xffffffffu, myci, bl);
        if (lane == k)  seli = cand_i;
        if (lane == bl) pi++;
    }

    // ---- exact rescore: serial fp32 fmaf chain, k ascending (R1-equivalent)
    float ev = -INFINITY;
    if (lane < TK && seli < Nn) {
        const float* xr = g_xn + (size_t)r   *Dd;
        const float* xc = g_xn + (size_t)seli*Dd;
        float acc = 0.f;
        #pragma unroll 16
        for (int k = 0; k < Dd; k++) acc = fmaf(xr[k], xc[k], acc);
        ev = acc;
    }

    // ---- warp bitonic sort by (ev desc, seli asc)  [jax top_k semantics]
    #pragma unroll
    for (int kk = 2; kk <= 32; kk <<= 1) {
        #pragma unroll
        for (int j = kk >> 1; j > 0; j >>= 1) {
            float ov = __shfl_xor_sync(0xffffffffu, ev,   j);
            int   oi = __shfl_xor_sync(0xffffffffu, seli, j);
            bool up         = ((lane & kk) == 0);
            bool lower      = ((lane & j)  == 0);
            bool takeBetter = (lower == up);
            bool mineBetter = (ev > ov) || (ev == ov && seli < oi);
            if (takeBetter != mineBetter) { ev = ov; seli = oi; }
        }
    }

    // ---- emit top-20 with exact weights
    if (lane < KNN) {
        g_topv[r*KNN + lane] = ev;
        g_topi[r*KNN + lane] = seli;
        atomicAdd(&g_deg[seli], ev);
    }
}

// =====================================================================
__global__ void k_dis() {
    int i = blockIdx.x*256 + threadIdx.x;
    if (i < Nn) {
        float dg = g_deg[i];
        g_dis[i] = (dg > 0.f) ? (1.f / sqrtf(fmaxf(dg, 1e-30f))) : 0.f;
    }
}

// =====================================================================
// dense transform: C[n, M] = A[n, 128] @ B[128, M]
// RELU flag applies ReLU to A at load (fuses layer-1 activation into gemm2).
template<int MDIM, int RELU>
__device__ __forceinline__ void gemm_body(const float* __restrict__ A,
                                          const float* __restrict__ B,
                                          float* __restrict__ C) {
    constexpr int TPR  = MDIM/32;
    constexpr int ROWS = 256/TPR;
    __shared__ float Bs[64][MDIM];
    int tid = threadIdx.x;
    int rr  = tid / TPR;
    int cc  = (tid % TPR)*32;
    int row = blockIdx.x*ROWS + rr;
    float acc[32];
    #pragma unroll
    for (int j = 0; j < 32; j++) acc[j] = 0.f;
    for (int kb = 0; kb < Dd; kb += 64) {
        #pragma unroll
        for (int t = 0; t < 64*MDIM/1024; t++) {
            int q = tid + t*256;
            int k = q/(MDIM/4), c = (q % (MDIM/4))*4;
            *(float4*)&Bs[k][c] = *(const float4*)&B[(kb+k)*MDIM + c];
        }
        __syncthreads();
        #pragma unroll 8
        for (int k = 0; k < 64; k++) {
            float a = A[row*Dd + kb + k];
            if (RELU) a = fmaxf(a, 0.f);
            #pragma unroll
            for (int j = 0; j < 32; j += 4) {
                float4 b = *(const float4*)&Bs[k][cc+j];
                acc[j+0] += a*b.x; acc[j+1] += a*b.y;
                acc[j+2] += a*b.z; acc[j+3] += a*b.w;
            }
        }
        __syncthreads();
    }
    #pragma unroll
    for (int j = 0; j < 32; j += 4)
        *(float4*)&C[row*MDIM + cc + j] =
            make_float4(acc[j],acc[j+1],acc[j+2],acc[j+3]);
}

__global__ void __launch_bounds__(256) k_gemm1(const float* __restrict__ x,
                                               const float* __restrict__ W1) {
    gemm_body<Dd, 0>(x, W1, g_hw1);
}
__global__ void __launch_bounds__(256) k_gemm2(const float* __restrict__ W2) {
    gemm_body<DOUT, 1>(g_hagg, W2, g_hw2);
}

// =====================================================================
// edge scatter: one warp per edge; dst[c] += dis[r]*w*dis[c] * src[r]
template<int F>
__device__ __forceinline__ void scatter_body(const float* __restrict__ src,
                                             float* __restrict__ dst) {
    int gw   = (blockIdx.x*256 + threadIdx.x) >> 5;
    int lane = threadIdx.x & 31;
    if (gw >= EE) return;
    int r = gw / KNN;
    int c = g_topi[gw];
    float nrm = g_dis[r] * g_topv[gw] * g_dis[c];
    constexpr int PER = F/32;
    const float* s = src + r*F + lane*PER;
    float*       d = dst + c*F + lane*PER;
    #pragma unroll
    for (int t = 0; t < PER; t++) atomicAdd(d + t, nrm * s[t]);
}

__global__ void k_scatter1() { scatter_body<Dd>(g_hw1, g_hagg); }
__global__ void k_scatter2(float* __restrict__ out) { scatter_body<DOUT>(g_hw2, out); }

// =====================================================================
extern "C" void kernel_launch(void* const* d_in, const int* in_sizes, int n_in,
                              void* d_out, int out_size) {
    const float* x  = (const float*)d_in[0];
    const float* W1 = (const float*)d_in[1];
    const float* b1 = (const float*)d_in[2];
    const float* W2 = (const float*)d_in[3];
    const float* b2 = (const float*)d_in[4];
    float* out = (float*)d_out;

    const int ADJ_SMEM = 4*128*TSTRIDE*4;   // 139264 bytes
    cudaFuncSetAttribute(k_adj, cudaFuncAttributeMaxDynamicSharedMemorySize, ADJ_SMEM);

    k_init    <<<(Nn*Dd)/256, 256>>>(b1, b2, out);
    k_rownorm <<<Nn/8, 256>>>(x);
    k_adj     <<<dim3(NTILES, NTILES), 256, ADJ_SMEM>>>();
    k_topk    <<<Nn/8, 256>>>();
    k_dis     <<<Nn/256, 256>>>();
    k_gemm1   <<<Nn/64, 256>>>(x, W1);
    k_scatter1<<<(EE*32)/256, 256>>>();
    k_gemm2   <<<Nn/128, 256>>>(W2);
    k_scatter2<<<(EE*32)/256, 256>>>(out);
}